// round 1
// baseline (speedup 1.0000x reference)
#include <cuda_runtime.h>

// out[128,1024] = x[128,1024] @ (w_pos - w_neg)[1024,1024] + (b_pos - b_neg)
// (all the memristor scaling cancels exactly: G_OFF cancels in the differential
//  pair, k_cond and K_V cancel in the final rescale, max_w never needed)

#define BATCH 128
#define NIN   1024
#define NOUT  1024
#define KSPLIT 16
#define KCHUNK 64      // NIN / KSPLIT
#define TILE_N 128
#define NT 8           // NOUT / TILE_N

// split-K partial accumulators (8 MB) — __device__ scratch, no allocation
__device__ float g_partial[KSPLIT * BATCH * NOUT];

__device__ __forceinline__ unsigned long long ffma2(unsigned long long a,
                                                    unsigned long long b,
                                                    unsigned long long c) {
    unsigned long long d;
    asm("fma.rn.f32x2 %0, %1, %2, %3;" : "=l"(d) : "l"(a), "l"(b), "l"(c));
    return d;
}

extern "C" __global__ void __launch_bounds__(512, 1)
memr_gemm_kernel(const float* __restrict__ x,
                 const float* __restrict__ wp,
                 const float* __restrict__ wn) {
    // dynamic smem: sA = 32 kpairs x 128 rows x float2 (32KB)
    //               sW = 32 kpairs x 128 cols x float2 (32KB)
    extern __shared__ float smem[];
    float* sA = smem;          // 8192 floats
    float* sW = smem + 8192;   // 8192 floats

    const int t  = threadIdx.x;
    const int jt = blockIdx.x;          // 0..7  (N tile)
    const int ks = blockIdx.y;          // 0..15 (K chunk)
    const int k0 = ks * KCHUNK;
    const int j0 = jt * TILE_N;

    // ---- load A tile: x[0:128, k0:k0+64] -> paired-k layout ----
    // 2048 float4 total, 4 per thread
#pragma unroll
    for (int r = 0; r < 4; r++) {
        int id  = t + 512 * r;
        int row = id >> 4;       // 16 float4 per row
        int kq  = id & 15;
        float4 v = *reinterpret_cast<const float4*>(x + row * NIN + k0 + kq * 4);
        int kk = kq * 2;
        *reinterpret_cast<float2*>(sA + (kk * 128 + row) * 2)       = make_float2(v.x, v.y);
        *reinterpret_cast<float2*>(sA + ((kk + 1) * 128 + row) * 2) = make_float2(v.z, v.w);
    }

    // ---- load W tile: (wp - wn)[k0:k0+64, j0:j0+128] -> paired-k layout ----
    // 2048 float4 per matrix, 4 per thread
#pragma unroll
    for (int r = 0; r < 4; r++) {
        int id   = t + 512 * r;
        int krow = id >> 5;      // 32 float4 per row
        int cq   = id & 31;
        const float4 p = *reinterpret_cast<const float4*>(wp + (k0 + krow) * NOUT + j0 + cq * 4);
        const float4 n = *reinterpret_cast<const float4*>(wn + (k0 + krow) * NOUT + j0 + cq * 4);
        int kk  = krow >> 1;
        int par = krow & 1;
        float* dst = sW + (kk * 128 + cq * 4) * 2 + par;
        dst[0] = p.x - n.x;
        dst[2] = p.y - n.y;
        dst[4] = p.z - n.z;
        dst[6] = p.w - n.w;
    }
    __syncthreads();

    // ---- main loop: per-thread 4 rows x 8 cols, packed even/odd-k accumulators ----
    const int tx = t & 15;   // col group: cols = tx + i*16   (conflict-free LDS)
    const int ty = t >> 4;   // row group: rows = ty + j*32

    unsigned long long acc[4][8];
#pragma unroll
    for (int j = 0; j < 4; j++)
#pragma unroll
        for (int i = 0; i < 8; i++) acc[j][i] = 0ull;

#pragma unroll 4
    for (int kk = 0; kk < 32; kk++) {
        unsigned long long a2[4], w2[8];
#pragma unroll
        for (int j = 0; j < 4; j++)
            a2[j] = *reinterpret_cast<const unsigned long long*>(
                sA + (kk * 128 + ty + j * 32) * 2);
#pragma unroll
        for (int i = 0; i < 8; i++)
            w2[i] = *reinterpret_cast<const unsigned long long*>(
                sW + (kk * 128 + tx + i * 16) * 2);
#pragma unroll
        for (int j = 0; j < 4; j++)
#pragma unroll
            for (int i = 0; i < 8; i++)
                acc[j][i] = ffma2(a2[j], w2[i], acc[j][i]);
    }

    // ---- epilogue: fold even/odd halves, write partial slice ----
    float* base = g_partial + ks * (BATCH * NOUT);
#pragma unroll
    for (int j = 0; j < 4; j++) {
        int row = ty + j * 32;
#pragma unroll
        for (int i = 0; i < 8; i++) {
            int col = j0 + tx + i * 16;
            unsigned lo = (unsigned)(acc[j][i] & 0xffffffffull);
            unsigned hi = (unsigned)(acc[j][i] >> 32);
            base[row * NOUT + col] = __uint_as_float(lo) + __uint_as_float(hi);
        }
    }
}

extern "C" __global__ void __launch_bounds__(256)
memr_reduce_kernel(const float* __restrict__ bp,
                   const float* __restrict__ bn,
                   float* __restrict__ out) {
    int id4  = blockIdx.x * 256 + threadIdx.x;   // 0..32767
    int base = id4 * 4;
    int o    = base & (NOUT - 1);

    float4 vp = *reinterpret_cast<const float4*>(bp + o);
    float4 vn = *reinterpret_cast<const float4*>(bn + o);
    float4 s  = make_float4(vp.x - vn.x, vp.y - vn.y, vp.z - vn.z, vp.w - vn.w);

#pragma unroll
    for (int k = 0; k < KSPLIT; k++) {
        float4 p = *reinterpret_cast<const float4*>(g_partial + k * (BATCH * NOUT) + base);
        s.x += p.x; s.y += p.y; s.z += p.z; s.w += p.w;
    }
    *reinterpret_cast<float4*>(out + base) = s;
}

extern "C" void kernel_launch(void* const* d_in, const int* in_sizes, int n_in,
                              void* d_out, int out_size) {
    const float* x  = (const float*)d_in[0];
    const float* wp = (const float*)d_in[1];
    const float* wn = (const float*)d_in[2];
    const float* bp = (const float*)d_in[3];
    const float* bn = (const float*)d_in[4];
    float* out = (float*)d_out;

    // 64KB dynamic smem opt-in (host-side attribute set; idempotent, capture-safe)
    cudaFuncSetAttribute(memr_gemm_kernel,
                         cudaFuncAttributeMaxDynamicSharedMemorySize, 65536);

    dim3 grid(NT, KSPLIT);
    memr_gemm_kernel<<<grid, 512, 65536>>>(x, wp, wn);
    memr_reduce_kernel<<<BATCH, 256>>>(bp, bn, out);
}

// round 3
// speedup vs baseline: 1.2786x; 1.2786x over previous
#include <cuda_runtime.h>
#include <cuda_bf16.h>
#include <cstdint>

// out[128,1024] = x[128,1024] @ (w_pos - w_neg)[1024,1024] + (b_pos - b_neg)
// All memristor scaling cancels exactly (G_OFF in the differential pair,
// k_cond & K_V in the rescale; max_w never needed).
//
// Tensor cores via baseline-PTX mma.sync (HMMA) — tcgen05 is rejected by this
// build's compute_103 PTX stage. bf16 hi/lo 3-term emulation:
//   x = xh + xl, d = dh + dl;  out ~= xh@dh + xh@dl + xl@dh  (xl@dl ~2^-16)

#define BATCH 128
#define NIN   1024
#define NOUT  1024
#define KSPLIT 8
#define KCHUNK 128      // NIN / KSPLIT
#define TILE_N 128
#define NT 8            // NOUT / TILE_N
#define RS 272          // padded smem row stride in bytes (256B data + 16B pad)

// split-K fp32 partials: 8 * 128 * 1024 floats = 4 MB (L2-resident)
__device__ float g_partial[KSPLIT * BATCH * NOUT];

__device__ __forceinline__ uint32_t smem_u32(const void* p) {
    uint32_t a;
    asm("{ .reg .u64 t; cvta.to.shared.u64 t, %1; cvt.u32.u64 %0, t; }" : "=r"(a) : "l"(p));
    return a;
}

__device__ __forceinline__ void split_hl(float v, uint16_t& h, uint16_t& l) {
    __nv_bfloat16 bh = __float2bfloat16(v);
    h = __bfloat16_as_ushort(bh);
    float r = v - __bfloat162float(bh);
    l = __bfloat16_as_ushort(__float2bfloat16(r));
}

__device__ __forceinline__ void ldsm4(uint32_t* r, uint32_t a) {
    asm volatile("ldmatrix.sync.aligned.m8n8.x4.shared.b16 {%0,%1,%2,%3}, [%4];"
                 : "=r"(r[0]), "=r"(r[1]), "=r"(r[2]), "=r"(r[3]) : "r"(a));
}
__device__ __forceinline__ void ldsm2(uint32_t* r, uint32_t a) {
    asm volatile("ldmatrix.sync.aligned.m8n8.x2.shared.b16 {%0,%1}, [%2];"
                 : "=r"(r[0]), "=r"(r[1]) : "r"(a));
}
__device__ __forceinline__ void mma16816(float* d, const uint32_t* a, const uint32_t* b) {
    asm volatile("mma.sync.aligned.m16n8k16.row.col.f32.bf16.bf16.f32 "
                 "{%0,%1,%2,%3}, {%4,%5,%6,%7}, {%8,%9}, {%0,%1,%2,%3};"
                 : "+f"(d[0]), "+f"(d[1]), "+f"(d[2]), "+f"(d[3])
                 : "r"(a[0]), "r"(a[1]), "r"(a[2]), "r"(a[3]),
                   "r"(b[0]), "r"(b[1]));
}

extern "C" __global__ void __launch_bounds__(256, 1)
memr_gemm_hmma(const float* __restrict__ x,
               const float* __restrict__ wp,
               const float* __restrict__ wn) {
    extern __shared__ char smem_raw[];
    const uint32_t base = smem_u32(smem_raw);
    const uint32_t Ah = base;                 // xh  [128 rows(b)][128 k] bf16, RS-padded
    const uint32_t Al = Ah + 128 * RS;        // xl
    const uint32_t Bh = Al + 128 * RS;        // dh^T [128 rows(o)][128 k]
    const uint32_t Bl = Bh + 128 * RS;        // dl^T

    const int t  = threadIdx.x;
    const int jt = blockIdx.x;        // N tile
    const int ks = blockIdx.y;        // K split
    const int k0 = ks * KCHUNK;
    const int j0 = jt * TILE_N;

    // ---- x tile: [128 b, k0:k0+128], coalesced float4, hi/lo split ----
#pragma unroll 4
    for (int i = 0; i < 16; i++) {
        int id  = t + 256 * i;
        int row = id >> 5;            // batch row
        int kq  = id & 31;            // float4 index within row
        float4 v = *reinterpret_cast<const float4*>(x + (size_t)row * NIN + k0 + kq * 4);
        uint16_t h0, h1, h2, h3, l0, l1, l2, l3;
        split_hl(v.x, h0, l0); split_hl(v.y, h1, l1);
        split_hl(v.z, h2, l2); split_hl(v.w, h3, l3);
        uint64_t hv = (uint64_t)((uint32_t)h0 | ((uint32_t)h1 << 16)) |
                      ((uint64_t)((uint32_t)h2 | ((uint32_t)h3 << 16)) << 32);
        uint64_t lv = (uint64_t)((uint32_t)l0 | ((uint32_t)l1 << 16)) |
                      ((uint64_t)((uint32_t)l2 | ((uint32_t)l3 << 16)) << 32);
        uint32_t off = (uint32_t)row * RS + (uint32_t)kq * 8;
        asm volatile("st.shared.b64 [%0], %1;" :: "r"(Ah + off), "l"(hv) : "memory");
        asm volatile("st.shared.b64 [%0], %1;" :: "r"(Al + off), "l"(lv) : "memory");
    }

    // ---- W tile: column-coalesced loads, transpose in regs -> [o][k] smem ----
    {
        const int o  = t & 127;       // output col within tile (row of B^T)
        const int kh = t >> 7;        // which k half (0/1)
#pragma unroll 2
        for (int kb = 0; kb < 8; kb++) {
            const int k8 = kh * 64 + kb * 8;
            const float* pw = wp + (size_t)(k0 + k8) * NOUT + j0 + o;
            const float* nw = wn + (size_t)(k0 + k8) * NOUT + j0 + o;
            float d[8];
#pragma unroll
            for (int i = 0; i < 8; i++) d[i] = pw[i * NOUT] - nw[i * NOUT];
            uint16_t h[8], l[8];
#pragma unroll
            for (int i = 0; i < 8; i++) split_hl(d[i], h[i], l[i]);
            uint32_t hv0 = (uint32_t)h[0] | ((uint32_t)h[1] << 16);
            uint32_t hv1 = (uint32_t)h[2] | ((uint32_t)h[3] << 16);
            uint32_t hv2 = (uint32_t)h[4] | ((uint32_t)h[5] << 16);
            uint32_t hv3 = (uint32_t)h[6] | ((uint32_t)h[7] << 16);
            uint32_t lv0 = (uint32_t)l[0] | ((uint32_t)l[1] << 16);
            uint32_t lv1 = (uint32_t)l[2] | ((uint32_t)l[3] << 16);
            uint32_t lv2 = (uint32_t)l[4] | ((uint32_t)l[5] << 16);
            uint32_t lv3 = (uint32_t)l[6] | ((uint32_t)l[7] << 16);
            uint32_t off = (uint32_t)o * RS + (uint32_t)k8 * 2;
            asm volatile("st.shared.v4.b32 [%0], {%1,%2,%3,%4};"
                         :: "r"(Bh + off), "r"(hv0), "r"(hv1), "r"(hv2), "r"(hv3) : "memory");
            asm volatile("st.shared.v4.b32 [%0], {%1,%2,%3,%4};"
                         :: "r"(Bl + off), "r"(lv0), "r"(lv1), "r"(lv2), "r"(lv3) : "memory");
        }
    }
    __syncthreads();

    // ---- compute: 8 warps in 4(M) x 2(N); each warp -> 32 rows x 64 cols ----
    const int wid  = t >> 5;
    const int lane = t & 31;
    const int wm = wid >> 1;          // 0..3 -> rows 32*wm
    const int wn2 = wid & 1;          // 0..1 -> cols 64*wn2

    float acc[2][8][4];
#pragma unroll
    for (int mt = 0; mt < 2; mt++)
#pragma unroll
        for (int nt = 0; nt < 8; nt++)
#pragma unroll
            for (int i = 0; i < 4; i++) acc[mt][nt][i] = 0.0f;

    // ldmatrix lane addressing
    const uint32_t aRowOff = (uint32_t)(wm * 32 + (lane & 15)) * RS + (uint32_t)((lane >> 4) * 16);
    const uint32_t bRowOff = (uint32_t)(wn2 * 64 + (lane & 7)) * RS + (uint32_t)(((lane >> 3) & 1) * 16);
    const uint32_t aH = Ah + aRowOff, aL = Al + aRowOff;
    const uint32_t bH = Bh + bRowOff, bL = Bl + bRowOff;

#pragma unroll 2
    for (int s = 0; s < 8; s++) {
        const uint32_t so = (uint32_t)s * 32;   // 16 bf16 = 32B per k-step
        uint32_t ah[2][4], al[2][4];
        ldsm4(ah[0], aH + so);
        ldsm4(ah[1], aH + 16 * RS + so);
        ldsm4(al[0], aL + so);
        ldsm4(al[1], aL + 16 * RS + so);
#pragma unroll
        for (int nt = 0; nt < 8; nt++) {
            uint32_t bh[2], bl[2];
            ldsm2(bh, bH + (uint32_t)(nt * 8) * RS + so);
            ldsm2(bl, bL + (uint32_t)(nt * 8) * RS + so);
#pragma unroll
            for (int mt = 0; mt < 2; mt++) {
                mma16816(acc[mt][nt], ah[mt], bh);
                mma16816(acc[mt][nt], ah[mt], bl);
                mma16816(acc[mt][nt], al[mt], bh);
            }
        }
    }

    // ---- epilogue: write 32x64 warp block to split-K partials ----
    float* dst = g_partial + (size_t)ks * (BATCH * NOUT);
    const int r0 = wm * 32 + (lane >> 2);
    const int c0 = j0 + wn2 * 64 + 2 * (lane & 3);
#pragma unroll
    for (int mt = 0; mt < 2; mt++) {
#pragma unroll
        for (int nt = 0; nt < 8; nt++) {
            int row = r0 + mt * 16;
            int col = c0 + nt * 8;
            float2 v01 = make_float2(acc[mt][nt][0], acc[mt][nt][1]);
            float2 v23 = make_float2(acc[mt][nt][2], acc[mt][nt][3]);
            *reinterpret_cast<float2*>(dst + (size_t)row * NOUT + col) = v01;
            *reinterpret_cast<float2*>(dst + (size_t)(row + 8) * NOUT + col) = v23;
        }
    }
}

extern "C" __global__ void __launch_bounds__(128)
memr_reduce_kernel(const float* __restrict__ bp,
                   const float* __restrict__ bn,
                   float* __restrict__ out) {
    int id   = blockIdx.x * 128 + threadIdx.x;   // 0..65535
    int base = id * 2;
    int o    = base & (NOUT - 1);

    float2 vp = *reinterpret_cast<const float2*>(bp + o);
    float2 vn = *reinterpret_cast<const float2*>(bn + o);
    float2 s  = make_float2(vp.x - vn.x, vp.y - vn.y);

#pragma unroll
    for (int k = 0; k < KSPLIT; k++) {
        float2 p = *reinterpret_cast<const float2*>(g_partial + (size_t)k * (BATCH * NOUT) + base);
        s.x += p.x; s.y += p.y;
    }
    *reinterpret_cast<float2*>(out + base) = s;
}

extern "C" void kernel_launch(void* const* d_in, const int* in_sizes, int n_in,
                              void* d_out, int out_size) {
    const float* x  = (const float*)d_in[0];
    const float* wp = (const float*)d_in[1];
    const float* wn = (const float*)d_in[2];
    const float* bp = (const float*)d_in[3];
    const float* bn = (const float*)d_in[4];
    float* out = (float*)d_out;

    // 139264B dynamic smem opt-in (idempotent, capture-safe; called every time)
    cudaFuncSetAttribute(memr_gemm_hmma,
                         cudaFuncAttributeMaxDynamicSharedMemorySize, 4 * 128 * RS);

    dim3 grid(NT, KSPLIT);
    memr_gemm_hmma<<<grid, 256, 4 * 128 * RS>>>(x, wp, wn);
    memr_reduce_kernel<<<512, 128>>>(bp, bn, out);
}

// round 4
// speedup vs baseline: 1.4800x; 1.1575x over previous
#include <cuda_runtime.h>
#include <cuda_bf16.h>
#include <cstdint>

// out[128,1024] = x[128,1024] @ (w_pos - w_neg)[1024,1024] + (b_pos - b_neg)
// Memristor scaling cancels exactly (G_OFF in the differential pair, k_cond &
// K_V in the rescale; max_w never needed).
// 3-term bf16 hi/lo emulation on HMMA (baseline PTX mma.sync; tcgen05 is
// rejected by this build's compute_103 PTX stage):
//   x = xh+xl, d = dh+dl;  out ~= xh@dh + xh@dl + xl@dh   (xl@dl ~2^-16)

#define BATCH 128
#define NIN   1024
#define NOUT  1024
#define KSPLIT 8
#define KCHUNK 128      // NIN / KSPLIT
#define TILE_N 64
#define NT 16           // NOUT / TILE_N
#define RA 272          // A smem row stride bytes (128 bf16 = 256B + 16 pad)
#define RB 144          // B smem row stride bytes (64 bf16 = 128B + 16 pad)

// split-K fp32 partials: 8 * 128 * 1024 floats = 4 MB (L2-resident)
__device__ float g_partial[KSPLIT * BATCH * NOUT];

__device__ __forceinline__ uint32_t smem_u32(const void* p) {
    uint32_t a;
    asm("{ .reg .u64 t; cvta.to.shared.u64 t, %1; cvt.u32.u64 %0, t; }" : "=r"(a) : "l"(p));
    return a;
}

__device__ __forceinline__ void split_hl(float v, uint16_t& h, uint16_t& l) {
    __nv_bfloat16 bh = __float2bfloat16(v);
    h = __bfloat16_as_ushort(bh);
    float r = v - __bfloat162float(bh);
    l = __bfloat16_as_ushort(__float2bfloat16(r));
}

__device__ __forceinline__ void ldsm4(uint32_t* r, uint32_t a) {
    asm volatile("ldmatrix.sync.aligned.m8n8.x4.shared.b16 {%0,%1,%2,%3}, [%4];"
                 : "=r"(r[0]), "=r"(r[1]), "=r"(r[2]), "=r"(r[3]) : "r"(a));
}
__device__ __forceinline__ void ldsm4t(uint32_t* r, uint32_t a) {
    asm volatile("ldmatrix.sync.aligned.m8n8.x4.trans.shared.b16 {%0,%1,%2,%3}, [%4];"
                 : "=r"(r[0]), "=r"(r[1]), "=r"(r[2]), "=r"(r[3]) : "r"(a));
}
__device__ __forceinline__ void mma16816(float* d, const uint32_t* a,
                                         uint32_t b0, uint32_t b1) {
    asm volatile("mma.sync.aligned.m16n8k16.row.col.f32.bf16.bf16.f32 "
                 "{%0,%1,%2,%3}, {%4,%5,%6,%7}, {%8,%9}, {%0,%1,%2,%3};"
                 : "+f"(d[0]), "+f"(d[1]), "+f"(d[2]), "+f"(d[3])
                 : "r"(a[0]), "r"(a[1]), "r"(a[2]), "r"(a[3]), "r"(b0), "r"(b1));
}

extern "C" __global__ void __launch_bounds__(256, 1)
memr_gemm_hmma(const float* __restrict__ x,
               const float* __restrict__ wp,
               const float* __restrict__ wn) {
    extern __shared__ char smem_raw[];
    const uint32_t Ah = smem_u32(smem_raw);       // xh [128 b][128 k] bf16
    const uint32_t Al = Ah + 128 * RA;            // xl
    const uint32_t Bh = Al + 128 * RA;            // dh [128 k][64 o] bf16
    const uint32_t Bl = Bh + 128 * RB;            // dl

    const int t  = threadIdx.x;
    const int jt = blockIdx.x;        // N tile (64 cols)
    const int ks = blockIdx.y;        // K split (128 k)
    const int k0 = ks * KCHUNK;
    const int j0 = jt * TILE_N;

    // ---- x tile: [128 b, k0:k0+128], coalesced float4, hi/lo split ----
#pragma unroll 4
    for (int i = 0; i < 16; i++) {
        int id  = t + 256 * i;
        int row = id >> 5;            // batch row (32 float4 per row)
        int kq  = id & 31;
        float4 v = *reinterpret_cast<const float4*>(x + (size_t)row * NIN + k0 + kq * 4);
        uint16_t h0, h1, h2, h3, l0, l1, l2, l3;
        split_hl(v.x, h0, l0); split_hl(v.y, h1, l1);
        split_hl(v.z, h2, l2); split_hl(v.w, h3, l3);
        uint64_t hv = (uint64_t)((uint32_t)h0 | ((uint32_t)h1 << 16)) |
                      ((uint64_t)((uint32_t)h2 | ((uint32_t)h3 << 16)) << 32);
        uint64_t lv = (uint64_t)((uint32_t)l0 | ((uint32_t)l1 << 16)) |
                      ((uint64_t)((uint32_t)l2 | ((uint32_t)l3 << 16)) << 32);
        uint32_t off = (uint32_t)row * RA + (uint32_t)kq * 8;
        asm volatile("st.shared.b64 [%0], %1;" :: "r"(Ah + off), "l"(hv) : "memory");
        asm volatile("st.shared.b64 [%0], %1;" :: "r"(Al + off), "l"(lv) : "memory");
    }

    // ---- W tile: row-major coalesced float4, diff+split, store [k][o] ----
#pragma unroll 4
    for (int i = 0; i < 8; i++) {
        int id = t + 256 * i;
        int k  = id >> 4;             // k row (16 float4 per row of 64 floats)
        int oq = id & 15;
        const float4 p = *reinterpret_cast<const float4*>(wp + (size_t)(k0 + k) * NOUT + j0 + oq * 4);
        const float4 n = *reinterpret_cast<const float4*>(wn + (size_t)(k0 + k) * NOUT + j0 + oq * 4);
        uint16_t h0, h1, h2, h3, l0, l1, l2, l3;
        split_hl(p.x - n.x, h0, l0); split_hl(p.y - n.y, h1, l1);
        split_hl(p.z - n.z, h2, l2); split_hl(p.w - n.w, h3, l3);
        uint64_t hv = (uint64_t)((uint32_t)h0 | ((uint32_t)h1 << 16)) |
                      ((uint64_t)((uint32_t)h2 | ((uint32_t)h3 << 16)) << 32);
        uint64_t lv = (uint64_t)((uint32_t)l0 | ((uint32_t)l1 << 16)) |
                      ((uint64_t)((uint32_t)l2 | ((uint32_t)l3 << 16)) << 32);
        uint32_t off = (uint32_t)k * RB + (uint32_t)oq * 8;
        asm volatile("st.shared.b64 [%0], %1;" :: "r"(Bh + off), "l"(hv) : "memory");
        asm volatile("st.shared.b64 [%0], %1;" :: "r"(Bl + off), "l"(lv) : "memory");
    }
    __syncthreads();

    // ---- compute: 8 warps as 4(M) x 2(N); warp tile 32 rows x 32 cols ----
    const int wid  = t >> 5;
    const int lane = t & 31;
    const int wm  = wid >> 1;         // 0..3 -> rows 32*wm
    const int wn2 = wid & 1;          // 0..1 -> cols 32*wn2

    float acc[2][4][4];
#pragma unroll
    for (int mt = 0; mt < 2; mt++)
#pragma unroll
        for (int n = 0; n < 4; n++)
#pragma unroll
            for (int i = 0; i < 4; i++) acc[mt][n][i] = 0.0f;

    // A (row-major) lane addr: row = wm*32 + (lane&15), 16B col chunk = lane>>4
    const uint32_t aOff = (uint32_t)(wm * 32 + (lane & 15)) * RA + (uint32_t)((lane >> 4) * 16);
    // B (x4.trans from [k][o]) lane addr: k row = lane&15, col = wn2*32 + (lane>>4)*8
    const uint32_t bOff = (uint32_t)(lane & 15) * RB + (uint32_t)(wn2 * 32 + (lane >> 4) * 8) * 2;
    const uint32_t aH = Ah + aOff, aL = Al + aOff;
    const uint32_t bH = Bh + bOff, bL = Bl + bOff;

#pragma unroll
    for (int s = 0; s < 8; s++) {
        const uint32_t soA = (uint32_t)s * 32;        // 16 bf16 = 32B along k
        const uint32_t soB = (uint32_t)(s * 16) * RB; // 16 k-rows down
        uint32_t ah[2][4], al[2][4];
        ldsm4(ah[0], aH + soA);
        ldsm4(ah[1], aH + 16 * RA + soA);
        ldsm4(al[0], aL + soA);
        ldsm4(al[1], aL + 16 * RA + soA);
        uint32_t bhr[2][4], blr[2][4];
        ldsm4t(bhr[0], bH + soB);
        ldsm4t(bhr[1], bH + soB + 32);    // cols +16
        ldsm4t(blr[0], bL + soB);
        ldsm4t(blr[1], bL + soB + 32);
#pragma unroll
        for (int n = 0; n < 4; n++) {
            const int g = n >> 1, j = n & 1;
            const uint32_t b0h = bhr[g][2 * j], b1h = bhr[g][2 * j + 1];
            const uint32_t b0l = blr[g][2 * j], b1l = blr[g][2 * j + 1];
#pragma unroll
            for (int mt = 0; mt < 2; mt++) {
                mma16816(acc[mt][n], ah[mt], b0h, b1h);
                mma16816(acc[mt][n], ah[mt], b0l, b1l);
                mma16816(acc[mt][n], al[mt], b0h, b1h);
            }
        }
    }

    // ---- epilogue: warp block 32x32 -> split-K partials (float2 stores) ----
    float* dst = g_partial + (size_t)ks * (BATCH * NOUT);
    const int r0 = wm * 32 + (lane >> 2);
    const int c0 = j0 + wn2 * 32 + 2 * (lane & 3);
#pragma unroll
    for (int mt = 0; mt < 2; mt++) {
#pragma unroll
        for (int n = 0; n < 4; n++) {
            int row = r0 + mt * 16;
            int col = c0 + n * 8;
            *reinterpret_cast<float2*>(dst + (size_t)row * NOUT + col) =
                make_float2(acc[mt][n][0], acc[mt][n][1]);
            *reinterpret_cast<float2*>(dst + (size_t)(row + 8) * NOUT + col) =
                make_float2(acc[mt][n][2], acc[mt][n][3]);
        }
    }
}

extern "C" __global__ void __launch_bounds__(128)
memr_reduce_kernel(const float* __restrict__ bp,
                   const float* __restrict__ bn,
                   float* __restrict__ out) {
    int id   = blockIdx.x * 128 + threadIdx.x;   // 0..32767
    int base = id * 4;
    int o    = base & (NOUT - 1);

    float4 vp = *reinterpret_cast<const float4*>(bp + o);
    float4 vn = *reinterpret_cast<const float4*>(bn + o);
    float4 s  = make_float4(vp.x - vn.x, vp.y - vn.y, vp.z - vn.z, vp.w - vn.w);

#pragma unroll
    for (int k = 0; k < KSPLIT; k++) {
        float4 p = *reinterpret_cast<const float4*>(g_partial + (size_t)k * (BATCH * NOUT) + base);
        s.x += p.x; s.y += p.y; s.z += p.z; s.w += p.w;
    }
    *reinterpret_cast<float4*>(out + base) = s;
}

extern "C" void kernel_launch(void* const* d_in, const int* in_sizes, int n_in,
                              void* d_out, int out_size) {
    const float* x  = (const float*)d_in[0];
    const float* wp = (const float*)d_in[1];
    const float* wn = (const float*)d_in[2];
    const float* bp = (const float*)d_in[3];
    const float* bn = (const float*)d_in[4];
    float* out = (float*)d_out;

    const int smem_bytes = 2 * 128 * RA + 2 * 128 * RB;   // 106496
    cudaFuncSetAttribute(memr_gemm_hmma,
                         cudaFuncAttributeMaxDynamicSharedMemorySize, smem_bytes);

    dim3 grid(NT, KSPLIT);
    memr_gemm_hmma<<<grid, 256, smem_bytes>>>(x, wp, wn);
    memr_reduce_kernel<<<256, 128>>>(bp, bn, out);
}